// round 17
// baseline (speedup 1.0000x reference)
#include <cuda_runtime.h>
#include <math.h>
#include <stdint.h>

#define B 16384
#define C 100
#define D 512
#define Z 128
#define BETA 50000000.0
#define EPSF 1e-8f

#define GRID        128          // 128 rows per CTA, exact
#define THREADS     544          // 16 consumer warps + 1 producer warp
#define NCONS       16
#define ROWS_CTA    128
#define NSTAGES     36           // 32 tube + 2 KL + 2 CE
#define NBUF        3

#define SLOT_BYTES  65536
#define SLOT_FLOATS (SLOT_BYTES / 4)
#define HALF_FLOATS 8192         // second array of the pair at +32KB
// barriers: full[0..2] then empty[0..2]
#define SMEM_BYTES  (NBUF * SLOT_BYTES + 64)   // 196672

__device__ double g_acc[3] = {0.0, 0.0, 0.0};
__device__ unsigned g_count = 0u;

__device__ __forceinline__ uint32_t smem_u32(const void* p) {
    uint32_t a;
    asm("{ .reg .u64 t; cvta.to.shared.u64 t, %1; cvt.u32.u64 %0, t; }" : "=r"(a) : "l"(p));
    return a;
}

__device__ __forceinline__ void bulk_cp(uint32_t dst, const void* src, uint32_t bytes, uint32_t bar) {
    asm volatile("cp.async.bulk.shared::cluster.global.mbarrier::complete_tx::bytes [%0], [%1], %2, [%3];"
                 :: "r"(dst), "l"(src), "r"(bytes), "r"(bar) : "memory");
}

__device__ __forceinline__ void mbar_wait(uint32_t bar, uint32_t parity) {
    uint32_t done;
    asm volatile("{ .reg .pred p; mbarrier.try_wait.parity.acquire.cta.shared::cta.b64 p, [%1], %2; selp.b32 %0, 1, 0, p; }"
                 : "=r"(done) : "r"(bar), "r"(parity) : "memory");
    if (!done) {
        asm volatile("{ .reg .pred P1; WL%=: mbarrier.try_wait.parity.acquire.cta.shared::cta.b64 P1, [%0], %1, 0x989680; @P1 bra.uni WD%=; bra.uni WL%=; WD%=: }"
                     :: "r"(bar), "r"(parity) : "memory");
    }
}

__device__ __forceinline__ void mbar_arrive(uint32_t bar) {
    asm volatile("mbarrier.arrive.release.cta.shared::cta.b64 _, [%0];" :: "r"(bar) : "memory");
}

__device__ __forceinline__ void mbar_expect(uint32_t bar, uint32_t bytes) {
    asm volatile("mbarrier.arrive.expect_tx.shared.b64 _, [%0], %1;"
                 :: "r"(bar), "r"(bytes) : "memory");
}

__device__ __forceinline__ float warp_sum(float v) {
#pragma unroll
    for (int o = 16; o; o >>= 1) v += __shfl_xor_sync(0xffffffffu, v, o);
    return v;
}

__device__ __forceinline__ float tube_scalar(float dot, float pp, float gg) {
    float p = sqrtf(pp);
    float g = sqrtf(gg);
    float denom = p * g;
    float cosine = (denom == 0.f) ? 0.f : (dot / denom);
    float s_s = 1.f - cosine * cosine;
    float sine = (s_s < 0.f) ? 0.f : sqrtf((s_s <= 0.f) ? EPSF : s_s);
    float gd = (g == 0.f) ? (g + EPSF) : g;
    float pc = p * cosine;
    float r_all = pc / gd;
    float ps = p * sine;
    float ds;
    if (r_all >= 1.f)       ds = 0.5f * (ps + fabsf(g - pc));
    else if (r_all >= 0.f)  ds = ps + fabsf(g - pc);
    else                    ds = 1.5f * fabsf(pc - g - ps);
    return -__logf(tanhf(1.f / ds));   // ds==0 -> inf -> tanh=1 -> 0, matches jax
}

extern __shared__ float smem[];

__global__ void __launch_bounds__(THREADS, 1)
loss_kernel(const float* __restrict__ fusion,
            const float* __restrict__ comple,
            const float* __restrict__ labels,
            const float* __restrict__ lab_enc,
            const float* __restrict__ xA,  const float* __restrict__ xAr,
            const float* __restrict__ xB,  const float* __restrict__ xBr,
            const float* __restrict__ xC,  const float* __restrict__ xCr,
            const float* __restrict__ mu,  const float* __restrict__ lv,
            float* __restrict__ out)
{
    const int tid  = threadIdx.x;
    const int warp = tid >> 5;
    const int lane = tid & 31;
    const int r_base = blockIdx.x * ROWS_CTA;

    const float* atts[4] = { xAr, xBr, xCr, comple };
    const float* labs[4] = { xA,  xB,  xC,  lab_enc };

    const uint32_t smem_base  = smem_u32(smem);
    const uint32_t full_base  = smem_base + NBUF * SLOT_BYTES;
    const uint32_t empty_base = full_base + NBUF * 8;

    if (tid == 0) {
#pragma unroll
        for (int k = 0; k < NBUF; k++) {
            asm volatile("mbarrier.init.shared.b64 [%0], 1;"  :: "r"(full_base  + k * 8) : "memory");
            asm volatile("mbarrier.init.shared.b64 [%0], %1;" :: "r"(empty_base + k * 8), "r"(NCONS) : "memory");
        }
        asm volatile("fence.proxy.async.shared::cta;" ::: "memory");
    }
    __syncthreads();

    float tube = 0.f, ce = 0.f, kl = 0.f;

    if (warp == NCONS) {
        // ---------------- producer warp ----------------
        if (lane == 0) {
            // stage t: t<32 -> tube (pair=t>>3, 16 rows chunk t&7), t<34 -> KL (64 rows), t<36 -> CE (64 rows)
            auto issue = [&](int t, int buf) {
                const uint32_t bar = full_base + buf * 8;
                const uint32_t dst = smem_base + buf * SLOT_BYTES;
                if (t < 32) {
                    const int pair = t >> 3;
                    const long r0 = r_base + (long)(t & 7) * 16;
                    mbar_expect(bar, 2 * 32768);
                    bulk_cp(dst,         atts[pair] + r0 * D, 32768, bar);   // 16 rows x 2KB contiguous
                    bulk_cp(dst + 32768, labs[pair] + r0 * D, 32768, bar);
                } else if (t < 34) {
                    const long r0 = r_base + (long)(t - 32) * 64;
                    mbar_expect(bar, 2 * 32768);
                    bulk_cp(dst,         mu + r0 * Z, 32768, bar);           // 64 rows x 512B contiguous
                    bulk_cp(dst + 32768, lv + r0 * Z, 32768, bar);
                } else {
                    const long r0 = r_base + (long)(t - 34) * 64;
                    mbar_expect(bar, 2 * 25600);
                    bulk_cp(dst,         fusion + r0 * C, 25600, bar);       // 64 rows x 400B contiguous
                    bulk_cp(dst + 25600, labels + r0 * C, 25600, bar);
                }
            };
#pragma unroll
            for (int k = 0; k < NBUF; k++) issue(k, k);
            for (int nx = NBUF; nx < NSTAGES; nx++) {
                const int buf = nx % NBUF;
                const uint32_t parity = ((nx / NBUF) - 1) & 1;
                mbar_wait(empty_base + buf * 8, parity);
                asm volatile("fence.proxy.async.shared::cta;" ::: "memory");
                issue(nx, buf);
            }
        }
    } else {
        // ---------------- consumer warps (0..15) ----------------
        int buf = 0;
        unsigned parity = 0;
        for (int t = 0; t < NSTAGES; t++) {
            mbar_wait(full_base + buf * 8, parity);
            const float* bufp = smem + buf * SLOT_FLOATS;

            if (t < 32) {
                // tube: warp processes row 'warp' of the 16-row chunk
                const float4* a4 = (const float4*)bufp + warp * (D / 4);
                const float4* g4 = (const float4*)(bufp + HALF_FLOATS) + warp * (D / 4);
                float dot = 0.f, pp = 0.f, gg = 0.f;
#pragma unroll
                for (int i = 0; i < 4; i++) {
                    float4 a = a4[lane + 32 * i];
                    float4 g = g4[lane + 32 * i];
                    dot += a.x * g.x + a.y * g.y + a.z * g.z + a.w * g.w;
                    pp  += a.x * a.x + a.y * a.y + a.z * a.z + a.w * a.w;
                    gg  += g.x * g.x + g.y * g.y + g.z * g.z + g.w * g.w;
                }
                dot = warp_sum(dot);
                pp  = warp_sum(pp);
                gg  = warp_sum(gg);
                tube += tube_scalar(dot, pp, gg);
            } else if (t < 34) {
                // KL: 64 rows, 4 rows per warp; row has Z=128 floats = 32 float4
                float kacc = 0.f;
#pragma unroll
                for (int k = 0; k < 4; k++) {
                    const int row = warp * 4 + k;
                    float4 m = ((const float4*)bufp)[row * 32 + lane];
                    float4 l = ((const float4*)(bufp + HALF_FLOATS))[row * 32 + lane];
                    kacc += (1.f + l.x - m.x * m.x - __expf(l.x))
                          + (1.f + l.y - m.y * m.y - __expf(l.y))
                          + (1.f + l.z - m.z * m.z - __expf(l.z))
                          + (1.f + l.w - m.w * m.w - __expf(l.w));
                }
                kl += warp_sum(kacc);
            } else {
                // CE: 64 rows, 4 rows per warp
#pragma unroll
                for (int k = 0; k < 4; k++) {
                    const int row = warp * 4 + k;
                    const float* f  = bufp + row * C;
                    const float* lb = bufp + 6400 + row * C;
                    float fmax = -INFINITY, lmax = -INFINITY;
                    int lidx = 0x7fffffff;
#pragma unroll
                    for (int q = 0; q < 4; q++) {
                        int i = lane + 32 * q;
                        if (i < C) {
                            float fv  = f[i];
                            float lvv = lb[i];
                            fmax = fmaxf(fmax, fv);
                            if (lvv > lmax || (lvv == lmax && i < lidx)) { lmax = lvv; lidx = i; }
                        }
                    }
#pragma unroll
                    for (int o = 16; o; o >>= 1) {
                        fmax = fmaxf(fmax, __shfl_xor_sync(0xffffffffu, fmax, o));
                        float ol = __shfl_xor_sync(0xffffffffu, lmax, o);
                        int   oi = __shfl_xor_sync(0xffffffffu, lidx, o);
                        if (ol > lmax || (ol == lmax && oi < lidx)) { lmax = ol; lidx = oi; }
                    }
                    float se = 0.f;
#pragma unroll
                    for (int q = 0; q < 4; q++) {
                        int i = lane + 32 * q;
                        if (i < C) se += __expf(f[i] - fmax);
                    }
                    se = warp_sum(se);
                    ce += -(f[lidx] - fmax - __logf(se));
                }
            }

            __syncwarp();
            if (lane == 0) mbar_arrive(empty_base + buf * 8);   // free this buffer

            if (++buf == NBUF) { buf = 0; parity ^= 1u; }
        }
    }

    // ---- block reduce + last-block finalize ----
    __shared__ float sT[17], sC[17], sK[17];
    if (lane == 0) { sT[warp] = tube; sC[warp] = ce; sK[warp] = kl; }
    __syncthreads();
    if (tid == 0) {
        float t = 0.f, c = 0.f, k = 0.f;
#pragma unroll
        for (int i = 0; i < NCONS; i++) { t += sT[i]; c += sC[i]; k += sK[i]; }
        atomicAdd(&g_acc[0], (double)t);
        atomicAdd(&g_acc[1], (double)c);
        atomicAdd(&g_acc[2], (double)k);
        __threadfence();
        unsigned prev = atomicAdd(&g_count, 1u);
        if (prev == gridDim.x - 1) {
            __threadfence();
            double tubeS = g_acc[0] / (double)B;                         // ALPHA = 1
            double ceS   = g_acc[1] / (double)B;
            double klS   = -0.5 * BETA * (g_acc[2] / ((double)B * (double)Z));
            out[0] = (float)(tubeS + ceS + klS);
            g_acc[0] = 0.0; g_acc[1] = 0.0; g_acc[2] = 0.0;
            g_count = 0u;
            __threadfence();
        }
    }
}

extern "C" void kernel_launch(void* const* d_in, const int* in_sizes, int n_in,
                              void* d_out, int out_size) {
    const float* fusion  = (const float*)d_in[0];
    const float* comple  = (const float*)d_in[1];
    const float* labels  = (const float*)d_in[2];
    const float* lab_enc = (const float*)d_in[3];
    const float* xA      = (const float*)d_in[4];
    const float* xAr     = (const float*)d_in[5];
    const float* xB      = (const float*)d_in[6];
    const float* xBr     = (const float*)d_in[7];
    const float* xC      = (const float*)d_in[8];
    const float* xCr     = (const float*)d_in[9];
    const float* mu      = (const float*)d_in[10];
    const float* lv      = (const float*)d_in[11];
    float* out = (float*)d_out;

    static int configured = 0;
    if (!configured) {
        cudaFuncSetAttribute(loss_kernel, cudaFuncAttributeMaxDynamicSharedMemorySize, SMEM_BYTES);
        configured = 1;
    }
    loss_kernel<<<GRID, THREADS, SMEM_BYTES>>>(fusion, comple, labels, lab_enc,
                                               xA, xAr, xB, xBr, xC, xCr, mu, lv, out);
}